// round 16
// baseline (speedup 1.0000x reference)
#include <cuda_runtime.h>
#include <cuda_fp16.h>
#include <cstdint>
#include <cstddef>

// ---------------- problem dims ----------------
#define BB   32
#define CIN  128
#define HH   64
#define WW   64
#define COUT 256
#define OH_  62
#define OW_  62
#define NPIX (BB * HH * WW)      // 131072 flat pixels
#define PADR 512                 // zero pad rows past the image (zero-init .bss)
#define XROWS (NPIX + PADR)

__device__ __align__(128) __half g_x[(size_t)XROWS * CIN];   // [pixel][c] fp16 (NHWC)
__device__ __align__(128) __half g_w[9 * COUT * CIN];        // [shift][n][c] fp16 (+-1)

// ---------------- helpers ----------------
__device__ __forceinline__ uint32_t smem_u32(const void* p) {
    uint32_t a;
    asm("{ .reg .u64 t; cvta.to.shared.u64 t, %1; cvt.u32.u64 %0, t; }" : "=r"(a) : "l"(p));
    return a;
}
__device__ __forceinline__ uint32_t swz(uint32_t off) {       // SW128 on 128B rows
    return off ^ ((off >> 3) & 0x70);
}

#define CP_ASYNC16(dst, src) \
    asm volatile("cp.async.cg.shared.global [%0], [%1], 16;" :: "r"(dst), "l"(src) : "memory")

// cp.async completion -> mbarrier arrive. .noinc: the completion-arrive
// counts AGAINST the init count (plain variant self-balances -> deadlock).
#define CP_ASYNC_MBAR_ARRIVE_NOINC(mbar) \
    asm volatile("cp.async.mbarrier.arrive.noinc.shared.b64 [%0];" :: "r"(mbar) : "memory")

#define MBAR_INIT(addr, cnt) \
    asm volatile("mbarrier.init.shared.b64 [%0], %1;" :: "r"(addr), "r"(cnt) : "memory")
#define MBAR_ARRIVE(addr) \
    asm volatile("mbarrier.arrive.shared.b64 _, [%0];" :: "r"(addr) : "memory")

__device__ __forceinline__ void mbar_wait(uint32_t addr, uint32_t parity) {
    uint32_t done;
    asm volatile(
        "{\n\t.reg .pred p;\n\t"
        "mbarrier.try_wait.parity.acquire.cta.shared::cta.b64 p, [%1], %2;\n\t"
        "selp.b32 %0, 1, 0, p;\n\t}"
        : "=r"(done) : "r"(addr), "r"(parity) : "memory");
    if (!done) {
        asm volatile(
            "{\n\t.reg .pred P1;\n\t"
            "WL_%=:\n\t"
            "mbarrier.try_wait.parity.acquire.cta.shared::cta.b64 P1, [%0], %1, 0x989680;\n\t"
            "@P1 bra.uni WD_%=;\n\t"
            "bra.uni WL_%=;\n\t"
            "WD_%=:\n\t}"
            :: "r"(addr), "r"(parity) : "memory");
    }
}

#define LDSM_X4(r0, r1, r2, r3, addr) \
    asm volatile("ldmatrix.sync.aligned.m8n8.x4.shared.b16 {%0,%1,%2,%3}, [%4];" \
        : "=r"(r0), "=r"(r1), "=r"(r2), "=r"(r3) : "r"(addr))

#define MMA16816(d, a, bb, c) \
    asm volatile("mma.sync.aligned.m16n8k16.row.col.f32.f16.f16.f32 " \
        "{%0,%1,%2,%3}, {%4,%5,%6,%7}, {%8,%9}, {%10,%11,%12,%13};" \
        : "=f"((d)[0]), "=f"((d)[1]), "=f"((d)[2]), "=f"((d)[3]) \
        : "r"((a)[0]), "r"((a)[1]), "r"((a)[2]), "r"((a)[3]), \
          "r"((bb)[0]), "r"((bb)[1]), \
          "f"((c)[0]), "f"((c)[1]), "f"((c)[2]), "f"((c)[3]))

// ---------------- prep kernels ----------------

// NCHW f32 -> [pixel][c] fp16 via smem transpose. One block per (b, h) row.
__global__ void __launch_bounds__(256) xpose_kernel(const float* __restrict__ x) {
    __shared__ __half s[128][65];
    int bid = blockIdx.x;
    int b = bid >> 6, hh = bid & 63;
    int tid = threadIdx.x;
    const float4* src = (const float4*)(x + (size_t)b * (CIN * HH * WW)
                                          + (size_t)hh * WW);
    #pragma unroll
    for (int i = tid; i < CIN * (WW / 4); i += 256) {   // float4 loads
        int c = i >> 4, w4 = i & 15;
        float4 v = src[(size_t)c * (HH * WW / 4) + w4];
        s[c][w4 * 4 + 0] = __float2half_rn(v.x);
        s[c][w4 * 4 + 1] = __float2half_rn(v.y);
        s[c][w4 * 4 + 2] = __float2half_rn(v.z);
        s[c][w4 * 4 + 3] = __float2half_rn(v.w);
    }
    __syncthreads();
    __half2* dst = (__half2*)(g_x + (size_t)bid * WW * CIN);
    #pragma unroll
    for (int i = tid; i < (CIN / 2) * WW; i += 256) {
        int c2 = (i & 63) * 2, w = i >> 6;
        dst[w * (CIN / 2) + (c2 >> 1)] = __halves2half2(s[c2][w], s[c2 + 1][w]);
    }
}

// W (256,128,3,3) f32 -> g_w[shift][n][c] fp16 with value 1-2W (exact +-1).
__global__ void wprep_kernel(const float* __restrict__ W) {
    int i = blockIdx.x * 256 + threadIdx.x;      // n*CIN + c
    if (i < COUT * CIN) {
        const float* p = W + (size_t)i * 9;
        #pragma unroll
        for (int s = 0; s < 9; s++)
            g_w[s * COUT * CIN + i] = __float2half_rn(1.0f - 2.0f * p[s]);
    }
}

// ---------------- GEMM kernel (warp-specialized, L2-traffic-minimal) ----------------
// C[M=131072, N=256] = A[M,K=1152] * W[N,K]^T
// Diagnosis: R13-15 are L2-BW bound (~9.9 TB/s demand vs ~11.3 TB/s LTS cap;
// traffic scales with tile splits). Fix: biggest tile -> minimum traffic.
// CTA tile: M=128, N=256 (full C_OUT) => 0.88 GB total (half of R13).
// 8 consumer warps (64x64 each, warp grid 2x4) + 2 producer warps = 320 thr.
// Stage: A 16KB + B 32KB = 48KB, 3 stages = 145KB -> 1 CTA/SM.
// Warp-spec mbarrier pipeline (no __syncthreads in main loop) preserves the
// R13 consumer-skew overlap.

static constexpr int NS = 3;
static constexpr int A_BYTES = 128 * 128;                // 16KB
static constexpr int STAGE_BYTES = A_BYTES + 256 * 128;  // 48KB
static constexpr int SMEM_BYTES = NS * STAGE_BYTES + 1024;
static constexpr int NCHUNK = 18;
static constexpr int NTHR = 320;                         // 8 consumers + 2 producers

__global__ void __launch_bounds__(NTHR, 1) gemm_kernel(float* __restrict__ out) {
    extern __shared__ char dynsmem[];
    __shared__ uint64_t s_full[NS];
    __shared__ uint64_t s_free[NS];
    uint32_t sm0 = (smem_u32(dynsmem) + 1023u) & ~1023u;
    uint32_t fullb = smem_u32(s_full);
    uint32_t freeb = smem_u32(s_free);

    int tid = threadIdx.x;
    int lane = tid & 31, wid = tid >> 5;

    int pbase = blockIdx.x * 128;          // flat pixel base (M tile); N covers all 256

    if (tid == 0) {
        #pragma unroll
        for (int s = 0; s < NS; s++) {
            MBAR_INIT(fullb + s * 8, 64);  // 64 producer-lane completion arrives
            MBAR_INIT(freeb + s * 8, 8);   // 8 consumer warps arrive
        }
    }
    __syncthreads();                        // only CTA-wide barrier (init)

    if (wid >= 8) {
        // ---------------- PRODUCER warps (wid 8,9) ----------------
        int pl = (wid - 8) * 32 + lane;     // 0..63
        for (int k = 0; k < NCHUNK; k++) {
            int st = k % NS, r = k / NS;
            if (k >= NS) mbar_wait(freeb + st * 8, (uint32_t)((r - 1) & 1));

            int s = k >> 1, h = k & 1;
            int kh = s / 3, kw = s - kh * 3;
            int pix0 = pbase + kh * WW + kw;
            const char* srcA = (const char*)g_x + (size_t)pix0 * (CIN * 2) + h * 128;
            const char* srcB = (const char*)g_w + (size_t)(s * COUT) * (CIN * 2) + h * 128;
            uint32_t sb = sm0 + st * STAGE_BYTES;
            #pragma unroll
            for (int i = 0; i < 16; i++) {           // A: 128 rows x 128B = 1024 x 16B
                int u = i * 64 + pl;
                int row = u >> 3, col = (u & 7) << 4;
                CP_ASYNC16(sb + swz((uint32_t)(row * 128 + col)),
                           srcA + (size_t)row * 256 + col);
            }
            #pragma unroll
            for (int i = 0; i < 32; i++) {           // B: 256 rows x 128B = 2048 x 16B
                int u = i * 64 + pl;
                int row = u >> 3, col = (u & 7) << 4;
                CP_ASYNC16(sb + A_BYTES + swz((uint32_t)(row * 128 + col)),
                           srcB + (size_t)row * 256 + col);
            }
            CP_ASYNC_MBAR_ARRIVE_NOINC(fullb + st * 8);  // fires when this lane's loads land
        }
        return;
    }

    // ---------------- CONSUMER warps (wid 0..7): 64x64 tiles, grid 2(M) x 4(N) ----------------
    int warp_m = wid & 1;
    int warp_n = wid >> 1;

    float acc[4][8][4];              // 128 regs
    #pragma unroll
    for (int i = 0; i < 4; i++)
        #pragma unroll
        for (int j = 0; j < 8; j++)
            #pragma unroll
            for (int q = 0; q < 4; q++) acc[i][j][q] = 0.0f;

    int lmat = lane >> 3;            // ldmatrix matrix index 0..3
    int lrow = lane & 7;             // row within 8x8
    int a_mrow = warp_m * 64 + (lmat & 1) * 8 + lrow;    // + mi*16
    int a_koff = (lmat >> 1) * 16;                       // + kk*32
    int b_nrow = warp_n * 64 + (lmat >> 1) * 8 + lrow;   // + nj2*16
    int b_koff = (lmat & 1) * 16;                        // + kk*32

    for (int k = 0; k < NCHUNK; k++) {
        int st = k % NS, r = k / NS;
        mbar_wait(fullb + st * 8, (uint32_t)(r & 1));

        uint32_t sA = sm0 + st * STAGE_BYTES;
        uint32_t sB = sA + A_BYTES;

        #pragma unroll
        for (int kk = 0; kk < 4; kk++) {         // 4 x k16 within 64 channels
            uint32_t a[4][4];
            uint32_t b[8][2];
            #pragma unroll
            for (int mi = 0; mi < 4; mi++)
                LDSM_X4(a[mi][0], a[mi][1], a[mi][2], a[mi][3],
                        sA + swz((uint32_t)((a_mrow + mi * 16) * 128
                                            + kk * 32 + a_koff)));
            #pragma unroll
            for (int nj2 = 0; nj2 < 4; nj2++) {
                uint32_t r0, r1, r2, r3;
                LDSM_X4(r0, r1, r2, r3,
                        sB + swz((uint32_t)((b_nrow + nj2 * 16) * 128
                                            + kk * 32 + b_koff)));
                b[nj2 * 2 + 0][0] = r0; b[nj2 * 2 + 0][1] = r1;
                b[nj2 * 2 + 1][0] = r2; b[nj2 * 2 + 1][1] = r3;
            }
            #pragma unroll
            for (int mi = 0; mi < 4; mi++)
                #pragma unroll
                for (int nj = 0; nj < 8; nj++)
                    MMA16816(acc[mi][nj], a[mi], b[nj], acc[mi][nj]);
        }

        __syncwarp();
        if (lane == 0) MBAR_ARRIVE(freeb + st * 8);   // this warp done with stage
    }

    // ---------------- epilogue ----------------
    // acc[mi][nj][q]: row = warp_m*64 + mi*16 + lane/4 + 8*(q>=2)
    //                 col = warp_n*64 + nj*8 + (lane%4)*2 + (q&1)
    int rbase = warp_m * 64 + (lane >> 2);
    int cbase = warp_n * 64 + (lane & 3) * 2;
    #pragma unroll
    for (int mi = 0; mi < 4; mi++) {
        #pragma unroll
        for (int half = 0; half < 2; half++) {
            int p = pbase + rbase + mi * 16 + half * 8;   // flat pixel
            int wo = p & 63, oh = (p >> 6) & 63, bb = p >> 12;
            if (wo >= OW_ || oh >= OH_) continue;
            float* obase = out + (size_t)bb * COUT * (OH_ * OW_)
                               + (size_t)oh * OW_ + wo;
            #pragma unroll
            for (int nj = 0; nj < 8; nj++) {
                int c = cbase + nj * 8;
                obase[(size_t)c * (OH_ * OW_)]       = acc[mi][nj][half * 2 + 0];
                obase[(size_t)(c + 1) * (OH_ * OW_)] = acc[mi][nj][half * 2 + 1];
            }
        }
    }
}

// ---------------- launch ----------------
extern "C" void kernel_launch(void* const* d_in, const int* in_sizes, int n_in,
                              void* d_out, int out_size) {
    const float* x = (const float*)d_in[0];
    const float* w = (const float*)d_in[1];
    if (n_in >= 2 && in_sizes[0] < in_sizes[1]) {   // defensive: x is the big tensor
        x = (const float*)d_in[1];
        w = (const float*)d_in[0];
    }
    float* out = (float*)d_out;

    cudaFuncSetAttribute(gemm_kernel, cudaFuncAttributeMaxDynamicSharedMemorySize, SMEM_BYTES);

    xpose_kernel<<<BB * HH, 256>>>(x);
    wprep_kernel<<<(COUT * CIN) / 256, 256>>>(w);
    gemm_kernel<<<NPIX / 128, NTHR, SMEM_BYTES>>>(out);
}

// round 17
// speedup vs baseline: 1.2411x; 1.2411x over previous
#include <cuda_runtime.h>
#include <cuda_fp16.h>
#include <cstdint>
#include <cstddef>

// ---------------- problem dims ----------------
#define BB   32
#define CIN  128
#define HH   64
#define WW   64
#define COUT 256
#define OH_  62
#define OW_  62
#define NPIX (BB * HH * WW)      // 131072 flat pixels
#define PADR 512                 // zero pad rows past the image (zero-init .bss)
#define XROWS (NPIX + PADR)

__device__ __align__(128) __half g_x[(size_t)XROWS * CIN];   // [pixel][c] fp16 (NHWC)
__device__ __align__(128) __half g_w[9 * COUT * CIN];        // [shift][n][c] fp16 (+-1)

// ---------------- helpers ----------------
__device__ __forceinline__ uint32_t smem_u32(const void* p) {
    uint32_t a;
    asm("{ .reg .u64 t; cvta.to.shared.u64 t, %1; cvt.u32.u64 %0, t; }" : "=r"(a) : "l"(p));
    return a;
}
__device__ __forceinline__ uint32_t swz(uint32_t off) {       // SW128 on 128B rows
    return off ^ ((off >> 3) & 0x70);
}

#define CP_ASYNC16(dst, src) \
    asm volatile("cp.async.cg.shared.global [%0], [%1], 16;" :: "r"(dst), "l"(src) : "memory")

// cp.async completion -> mbarrier arrive. .noinc: the completion-arrive
// counts AGAINST the init count (plain variant self-balances -> deadlock).
#define CP_ASYNC_MBAR_ARRIVE_NOINC(mbar) \
    asm volatile("cp.async.mbarrier.arrive.noinc.shared.b64 [%0];" :: "r"(mbar) : "memory")

#define MBAR_INIT(addr, cnt) \
    asm volatile("mbarrier.init.shared.b64 [%0], %1;" :: "r"(addr), "r"(cnt) : "memory")
#define MBAR_ARRIVE(addr) \
    asm volatile("mbarrier.arrive.shared.b64 _, [%0];" :: "r"(addr) : "memory")

__device__ __forceinline__ void mbar_wait(uint32_t addr, uint32_t parity) {
    uint32_t done;
    asm volatile(
        "{\n\t.reg .pred p;\n\t"
        "mbarrier.try_wait.parity.acquire.cta.shared::cta.b64 p, [%1], %2;\n\t"
        "selp.b32 %0, 1, 0, p;\n\t}"
        : "=r"(done) : "r"(addr), "r"(parity) : "memory");
    if (!done) {
        asm volatile(
            "{\n\t.reg .pred P1;\n\t"
            "WL_%=:\n\t"
            "mbarrier.try_wait.parity.acquire.cta.shared::cta.b64 P1, [%0], %1, 0x989680;\n\t"
            "@P1 bra.uni WD_%=;\n\t"
            "bra.uni WL_%=;\n\t"
            "WD_%=:\n\t}"
            :: "r"(addr), "r"(parity) : "memory");
    }
}

#define LDSM_X4(r0, r1, r2, r3, addr) \
    asm volatile("ldmatrix.sync.aligned.m8n8.x4.shared.b16 {%0,%1,%2,%3}, [%4];" \
        : "=r"(r0), "=r"(r1), "=r"(r2), "=r"(r3) : "r"(addr))

#define MMA16816(d, a, bb, c) \
    asm volatile("mma.sync.aligned.m16n8k16.row.col.f32.f16.f16.f32 " \
        "{%0,%1,%2,%3}, {%4,%5,%6,%7}, {%8,%9}, {%10,%11,%12,%13};" \
        : "=f"((d)[0]), "=f"((d)[1]), "=f"((d)[2]), "=f"((d)[3]) \
        : "r"((a)[0]), "r"((a)[1]), "r"((a)[2]), "r"((a)[3]), \
          "r"((bb)[0]), "r"((bb)[1]), \
          "f"((c)[0]), "f"((c)[1]), "f"((c)[2]), "f"((c)[3]))

// streaming store hint: output is written once, keep it out of L2's way
#define STG_CS(ptr, val) \
    asm volatile("st.global.cs.f32 [%0], %1;" :: "l"(ptr), "f"(val) : "memory")

// ---------------- prep kernels ----------------

// NCHW f32 -> [pixel][c] fp16 via smem transpose. One block per (b, h) row.
// launch_bounds(256,8): regs<=32 so the RF admits 8 blocks (full 64-warp cap);
// this kernel is memory-latency bound (51% DRAM at 6 blocks/SM).
__global__ void __launch_bounds__(256, 8) xpose_kernel(const float* __restrict__ x) {
    __shared__ __half s[128][65];
    int bid = blockIdx.x;
    int b = bid >> 6, hh = bid & 63;
    int tid = threadIdx.x;
    const float4* src = (const float4*)(x + (size_t)b * (CIN * HH * WW)
                                          + (size_t)hh * WW);
    #pragma unroll
    for (int i = tid; i < CIN * (WW / 4); i += 256) {   // float4 loads
        int c = i >> 4, w4 = i & 15;
        float4 v = src[(size_t)c * (HH * WW / 4) + w4];
        s[c][w4 * 4 + 0] = __float2half_rn(v.x);
        s[c][w4 * 4 + 1] = __float2half_rn(v.y);
        s[c][w4 * 4 + 2] = __float2half_rn(v.z);
        s[c][w4 * 4 + 3] = __float2half_rn(v.w);
    }
    __syncthreads();
    __half2* dst = (__half2*)(g_x + (size_t)bid * WW * CIN);
    #pragma unroll
    for (int i = tid; i < (CIN / 2) * WW; i += 256) {
        int c2 = (i & 63) * 2, w = i >> 6;
        dst[w * (CIN / 2) + (c2 >> 1)] = __halves2half2(s[c2][w], s[c2 + 1][w]);
    }
}

// W (256,128,3,3) f32 -> g_w[shift][n][c] fp16 with value 1-2W (exact +-1).
__global__ void wprep_kernel(const float* __restrict__ W) {
    int i = blockIdx.x * 256 + threadIdx.x;      // n*CIN + c
    if (i < COUT * CIN) {
        const float* p = W + (size_t)i * 9;
        #pragma unroll
        for (int s = 0; s < 9; s++)
            g_w[s * COUT * CIN + i] = __float2half_rn(1.0f - 2.0f * p[s]);
    }
}

// ---------------- GEMM kernel (R13/R14 config — measured optimum) ----------------
// C[M=131072, N=256] = A[M,K=1152] * W[N,K]^T
// 3 warp-specialized CTAs/SM. CTA tile: M=64, N=128.
// 4 consumer warps (64x32 each) + 1 producer = 160 thr.
// Stage: A 8KB + B 16KB = 24KB, 3 stages = 72KB/CTA. No __syncthreads in
// the main loop (mbarrier full/free pipeline; consumer warps skew freely).

static constexpr int NS = 3;
static constexpr int A_BYTES = 64 * 128;                 // 8KB
static constexpr int STAGE_BYTES = A_BYTES + 128 * 128;  // 24KB
static constexpr int SMEM_BYTES = NS * STAGE_BYTES + 1024;
static constexpr int NCHUNK = 18;
static constexpr int NTHR = 160;                         // 4 consumers + 1 producer

__global__ void __launch_bounds__(NTHR, 3) gemm_kernel(float* __restrict__ out) {
    extern __shared__ char dynsmem[];
    __shared__ uint64_t s_full[NS];
    __shared__ uint64_t s_free[NS];
    uint32_t sm0 = (smem_u32(dynsmem) + 1023u) & ~1023u;
    uint32_t fullb = smem_u32(s_full);
    uint32_t freeb = smem_u32(s_free);

    int tid = threadIdx.x;
    int lane = tid & 31, wid = tid >> 5;

    int pbase = (blockIdx.x >> 1) * 64;    // flat pixel base (M tile)
    int nbase = (blockIdx.x & 1) * 128;    // output-channel base (N tile)

    if (tid == 0) {
        #pragma unroll
        for (int s = 0; s < NS; s++) {
            MBAR_INIT(fullb + s * 8, 32);  // 32 producer-lane completion arrives
            MBAR_INIT(freeb + s * 8, 4);   // 4 consumer warps arrive
        }
    }
    __syncthreads();                        // only CTA-wide barrier (init)

    if (wid == 4) {
        // ---------------- PRODUCER warp ----------------
        for (int k = 0; k < NCHUNK; k++) {
            int st = k % NS, r = k / NS;
            if (k >= NS) mbar_wait(freeb + st * 8, (uint32_t)((r - 1) & 1));

            int s = k >> 1, h = k & 1;
            int kh = s / 3, kw = s - kh * 3;
            int pix0 = pbase + kh * WW + kw;
            const char* srcA = (const char*)g_x + (size_t)pix0 * (CIN * 2) + h * 128;
            const char* srcB = (const char*)g_w
                + (size_t)(s * COUT + nbase) * (CIN * 2) + h * 128;
            uint32_t sb = sm0 + st * STAGE_BYTES;
            #pragma unroll
            for (int i = 0; i < 16; i++) {           // A: 64 rows x 128B = 512 x 16B
                int u = i * 32 + lane;
                int row = u >> 3, col = (u & 7) << 4;
                CP_ASYNC16(sb + swz((uint32_t)(row * 128 + col)),
                           srcA + (size_t)row * 256 + col);
            }
            #pragma unroll
            for (int i = 0; i < 32; i++) {           // B: 128 rows x 128B = 1024 x 16B
                int u = i * 32 + lane;
                int row = u >> 3, col = (u & 7) << 4;
                CP_ASYNC16(sb + A_BYTES + swz((uint32_t)(row * 128 + col)),
                           srcB + (size_t)row * 256 + col);
            }
            CP_ASYNC_MBAR_ARRIVE_NOINC(fullb + st * 8);  // fires when this lane's loads land
        }
        return;
    }

    // ---------------- CONSUMER warps (wid 0..3) ----------------
    int warp_n = wid;                // 32-col slice; warp_m = 0 (M=64)

    float acc[4][4][4];              // 64 regs
    #pragma unroll
    for (int i = 0; i < 4; i++)
        #pragma unroll
        for (int j = 0; j < 4; j++)
            #pragma unroll
            for (int q = 0; q < 4; q++) acc[i][j][q] = 0.0f;

    int lmat = lane >> 3;            // ldmatrix matrix index 0..3
    int lrow = lane & 7;             // row within 8x8
    int a_mrow = (lmat & 1) * 8 + lrow;                  // + mi*16
    int a_koff = (lmat >> 1) * 16;                       // + kk*32
    int b_nrow = warp_n * 32 + (lmat >> 1) * 8 + lrow;   // + nj2*16
    int b_koff = (lmat & 1) * 16;                        // + kk*32

    for (int k = 0; k < NCHUNK; k++) {
        int st = k % NS, r = k / NS;
        mbar_wait(fullb + st * 8, (uint32_t)(r & 1));

        uint32_t sA = sm0 + st * STAGE_BYTES;
        uint32_t sB = sA + A_BYTES;

        #pragma unroll
        for (int kk = 0; kk < 4; kk++) {         // 4 x k16 within 64 channels
            uint32_t a[4][4];
            uint32_t b[4][2];
            #pragma unroll
            for (int mi = 0; mi < 4; mi++)
                LDSM_X4(a[mi][0], a[mi][1], a[mi][2], a[mi][3],
                        sA + swz((uint32_t)((a_mrow + mi * 16) * 128
                                            + kk * 32 + a_koff)));
            #pragma unroll
            for (int nj2 = 0; nj2 < 2; nj2++) {
                uint32_t r0, r1, r2, r3;
                LDSM_X4(r0, r1, r2, r3,
                        sB + swz((uint32_t)((b_nrow + nj2 * 16) * 128
                                            + kk * 32 + b_koff)));
                b[nj2 * 2 + 0][0] = r0; b[nj2 * 2 + 0][1] = r1;
                b[nj2 * 2 + 1][0] = r2; b[nj2 * 2 + 1][1] = r3;
            }
            #pragma unroll
            for (int mi = 0; mi < 4; mi++)
                #pragma unroll
                for (int nj = 0; nj < 4; nj++)
                    MMA16816(acc[mi][nj], a[mi], b[nj], acc[mi][nj]);
        }

        __syncwarp();
        if (lane == 0) MBAR_ARRIVE(freeb + st * 8);   // this warp done with stage
    }

    // ---------------- epilogue (streaming stores) ----------------
    // acc[mi][nj][q]: row = mi*16 + lane/4 + 8*(q>=2)
    //                 col = nbase + warp_n*32 + nj*8 + (lane%4)*2 + (q&1)
    int rbase = lane >> 2;
    int cbase = nbase + warp_n * 32 + (lane & 3) * 2;
    #pragma unroll
    for (int mi = 0; mi < 4; mi++) {
        #pragma unroll
        for (int half = 0; half < 2; half++) {
            int p = pbase + rbase + mi * 16 + half * 8;   // flat pixel
            int wo = p & 63, oh = (p >> 6) & 63, bb = p >> 12;
            if (wo >= OW_ || oh >= OH_) continue;
            float* obase = out + (size_t)bb * COUT * (OH_ * OW_)
                               + (size_t)oh * OW_ + wo;
            #pragma unroll
            for (int nj = 0; nj < 4; nj++) {
                int c = cbase + nj * 8;
                STG_CS(obase + (size_t)c * (OH_ * OW_),       acc[mi][nj][half * 2 + 0]);
                STG_CS(obase + (size_t)(c + 1) * (OH_ * OW_), acc[mi][nj][half * 2 + 1]);
            }
        }
    }
}

// ---------------- launch ----------------
extern "C" void kernel_launch(void* const* d_in, const int* in_sizes, int n_in,
                              void* d_out, int out_size) {
    const float* x = (const float*)d_in[0];
    const float* w = (const float*)d_in[1];
    if (n_in >= 2 && in_sizes[0] < in_sizes[1]) {   // defensive: x is the big tensor
        x = (const float*)d_in[1];
        w = (const float*)d_in[0];
    }
    float* out = (float*)d_out;

    cudaFuncSetAttribute(gemm_kernel, cudaFuncAttributeMaxDynamicSharedMemorySize, SMEM_BYTES);

    xpose_kernel<<<BB * HH, 256>>>(x);
    wprep_kernel<<<(COUT * CIN) / 256, 256>>>(w);
    gemm_kernel<<<(NPIX / 64) * 2, NTHR, SMEM_BYTES>>>(out);
}